// round 1
// baseline (speedup 1.0000x reference)
#include <cuda_runtime.h>
#include <cuda_bf16.h>

// Problem constants (shapes are fixed by the dataset)
#define MAXN 50000
#define MAXE 800000
#define CCH  64
#define NGRAPH 128

// Scratch (device globals; no runtime allocation allowed)
__device__ float g_h[MAXN * CCH];
__device__ float g_t[MAXN * CCH];
__device__ float g_agg[MAXN * CCH];
__device__ float g_EA[MAXN * 12];
__device__ float g_sums[NGRAPH];
__device__ float g_counts[NGRAPH];

__device__ __forceinline__ void red_add_v4(float* addr, float4 v) {
    asm volatile("red.global.add.v4.f32 [%0], {%1,%2,%3,%4};"
                 :: "l"(addr), "f"(v.x), "f"(v.y), "f"(v.z), "f"(v.w)
                 : "memory");
}

__device__ __forceinline__ float lrelu(float a) {
    return a > 0.0f ? a : 0.01f * a;
}

// ---------------------------------------------------------------------------
// Read-in: h = leaky_relu([state|action] @ W_in + b_in).  Warp per node.
// Lane owns output channels (2*lane, 2*lane+1).
// ---------------------------------------------------------------------------
__global__ void k_readin(const float* __restrict__ state,
                         const float* __restrict__ action,
                         const float* __restrict__ W,   // [12,64]
                         const float* __restrict__ b,   // [64]
                         float* __restrict__ h, int N) {
    __shared__ float Ws[12 * 64];
    __shared__ float bs[64];
    int tid = threadIdx.x;
    for (int i = tid; i < 12 * 64; i += 256) Ws[i] = W[i];
    if (tid < 64) bs[tid] = b[tid];
    __syncthreads();
    int warp = tid >> 5, lane = tid & 31;
    int n = blockIdx.x * 8 + warp;
    if (n >= N) return;

    float x = 0.0f;
    if (lane < 8)        x = state[n * 8 + lane];
    else if (lane < 12)  x = action[n * 4 + (lane - 8)];

    float a0 = bs[2 * lane], a1 = bs[2 * lane + 1];
    const float2* W2 = (const float2*)Ws;
#pragma unroll
    for (int k = 0; k < 12; k++) {
        float a = __shfl_sync(0xffffffffu, x, k);
        float2 w = W2[k * 32 + lane];
        a0 += a * w.x; a1 += a * w.y;
    }
    ((float2*)h)[n * 32 + lane] = make_float2(lrelu(a0), lrelu(a1));
}

// ---------------------------------------------------------------------------
// EA = segment_sum(edge_attr, dst). edge_attr row = 12 floats = 3 float4.
// One thread per (edge, quarter).
// ---------------------------------------------------------------------------
__global__ void k_ea(const int* __restrict__ ei, const float* __restrict__ edge_attr,
                     float* __restrict__ EA, int E) {
    int idx = blockIdx.x * 256 + threadIdx.x;
    if (idx >= E * 3) return;
    int e = idx / 3;
    int j = idx - e * 3;
    int dst = ei[E + e];
    float4 v = ((const float4*)edge_attr)[e * 3 + j];
    red_add_v4(EA + dst * 12 + j * 4, v);
}

// ---------------------------------------------------------------------------
// t = h @ W_nbr[l].  Warp per node, W in shared.
// ---------------------------------------------------------------------------
__global__ void k_matnbr(const float* __restrict__ h, const float* __restrict__ W,
                         float* __restrict__ t, int N) {
    __shared__ float Ws[64 * 64];
    int tid = threadIdx.x;
    for (int i = tid; i < 4096; i += 256) Ws[i] = W[i];
    __syncthreads();
    int warp = tid >> 5, lane = tid & 31;
    int n = blockIdx.x * 8 + warp;
    if (n >= N) return;

    float h0 = h[n * 64 + lane];
    float h1 = h[n * 64 + 32 + lane];
    float a0 = 0.0f, a1 = 0.0f;
    const float2* W2 = (const float2*)Ws;
#pragma unroll
    for (int k = 0; k < 32; k++) {
        float a = __shfl_sync(0xffffffffu, h0, k);
        float2 w = W2[k * 32 + lane];
        a0 += a * w.x; a1 += a * w.y;
    }
#pragma unroll
    for (int k = 0; k < 32; k++) {
        float a = __shfl_sync(0xffffffffu, h1, k);
        float2 w = W2[(k + 32) * 32 + lane];
        a0 += a * w.x; a1 += a * w.y;
    }
    ((float2*)t)[n * 32 + lane] = make_float2(a0, a1);
}

// ---------------------------------------------------------------------------
// Edge scatter: agg[dst] += t[src], 64 floats per edge = 16 float4.
// 16 threads per edge; vector L2 reductions (t/agg are L2-resident).
// ---------------------------------------------------------------------------
__global__ void k_scatter(const int* __restrict__ ei, const float* __restrict__ t,
                          float* __restrict__ agg, int E) {
    int idx = blockIdx.x * 256 + threadIdx.x;
    if (idx >= E * 16) return;
    int e = idx >> 4;
    int g = idx & 15;
    int src = ei[e];
    int dst = ei[E + e];
    float4 v = ((const float4*)t)[src * 16 + g];
    red_add_v4(agg + dst * 64 + g * 4, v);
}

// ---------------------------------------------------------------------------
// h = leaky_relu(h @ W_self[l] + agg + EA @ W_edge[l] + b_conv[l]).
// Warp per node; W_self + W_edge in shared.
// ---------------------------------------------------------------------------
__global__ void k_update(float* __restrict__ h, const float* __restrict__ agg,
                         const float* __restrict__ EA,
                         const float* __restrict__ Wself,   // [64,64]
                         const float* __restrict__ Wedge,   // [12,64]
                         const float* __restrict__ bconv,   // [64]
                         int N) {
    __shared__ float Ws[64 * 64];
    __shared__ float We[12 * 64];
    __shared__ float bs[64];
    int tid = threadIdx.x;
    for (int i = tid; i < 4096; i += 256) Ws[i] = Wself[i];
    for (int i = tid; i < 768; i += 256)  We[i] = Wedge[i];
    if (tid < 64) bs[tid] = bconv[tid];
    __syncthreads();
    int warp = tid >> 5, lane = tid & 31;
    int n = blockIdx.x * 8 + warp;
    if (n >= N) return;

    float h0 = h[n * 64 + lane];
    float h1 = h[n * 64 + 32 + lane];
    float ea = (lane < 12) ? EA[n * 12 + lane] : 0.0f;
    float2 ag = ((const float2*)agg)[n * 32 + lane];
    float a0 = ag.x + bs[2 * lane];
    float a1 = ag.y + bs[2 * lane + 1];

    const float2* W2 = (const float2*)Ws;
#pragma unroll
    for (int k = 0; k < 32; k++) {
        float a = __shfl_sync(0xffffffffu, h0, k);
        float2 w = W2[k * 32 + lane];
        a0 += a * w.x; a1 += a * w.y;
    }
#pragma unroll
    for (int k = 0; k < 32; k++) {
        float a = __shfl_sync(0xffffffffu, h1, k);
        float2 w = W2[(k + 32) * 32 + lane];
        a0 += a * w.x; a1 += a * w.y;
    }
    const float2* We2 = (const float2*)We;
#pragma unroll
    for (int k = 0; k < 12; k++) {
        float a = __shfl_sync(0xffffffffu, ea, k);
        float2 w = We2[k * 32 + lane];
        a0 += a * w.x; a1 += a * w.y;
    }
    ((float2*)h)[n * 32 + lane] = make_float2(lrelu(a0), lrelu(a1));
}

// ---------------------------------------------------------------------------
// Readout: y = h @ W_out + b_out per node; scatter-add into per-graph sums/counts.
// ---------------------------------------------------------------------------
__global__ void k_readout(const float* __restrict__ h, const float* __restrict__ Wout,
                          const float* __restrict__ bout, const int* __restrict__ batch,
                          float* __restrict__ sums, float* __restrict__ counts, int N) {
    __shared__ float Ws[64];
    if (threadIdx.x < 64) Ws[threadIdx.x] = Wout[threadIdx.x];
    __syncthreads();
    int warp = threadIdx.x >> 5, lane = threadIdx.x & 31;
    int n = blockIdx.x * 8 + warp;
    if (n >= N) return;
    float p = h[n * 64 + lane] * Ws[lane] + h[n * 64 + 32 + lane] * Ws[32 + lane];
#pragma unroll
    for (int o = 16; o > 0; o >>= 1) p += __shfl_down_sync(0xffffffffu, p, o);
    if (lane == 0) {
        int b = batch[n];
        atomicAdd(&sums[b], p + bout[0]);
        atomicAdd(&counts[b], 1.0f);
    }
}

__global__ void k_final(const float* __restrict__ sums, const float* __restrict__ counts,
                        float* __restrict__ out, int G) {
    int i = blockIdx.x * 128 + threadIdx.x;
    if (i < G) out[i] = sums[i] / fmaxf(counts[i], 1.0f);
}

// ---------------------------------------------------------------------------
extern "C" void kernel_launch(void* const* d_in, const int* in_sizes, int n_in,
                              void* d_out, int out_size) {
    const float* state     = (const float*)d_in[0];
    const float* action    = (const float*)d_in[1];
    const int*   edge_idx  = (const int*)d_in[2];      // int64 in ref is canonicalized to int32 by jax
    const float* edge_attr = (const float*)d_in[3];
    const int*   batch     = (const int*)d_in[4];
    const float* W_in      = (const float*)d_in[5];
    const float* b_in      = (const float*)d_in[6];
    const float* W_self    = (const float*)d_in[7];    // [2,64,64]
    const float* W_nbr     = (const float*)d_in[8];    // [2,64,64]
    const float* W_edge    = (const float*)d_in[9];    // [2,12,64]
    const float* b_conv    = (const float*)d_in[10];   // [2,64]
    const float* W_out     = (const float*)d_in[11];   // [64,1]
    const float* b_out     = (const float*)d_in[12];   // [1]
    float* out = (float*)d_out;

    const int N = in_sizes[0] / 8;
    const int E = in_sizes[3] / 12;
    const int G = out_size;

    float *h_p, *t_p, *agg_p, *ea_p, *sums_p, *counts_p;
    cudaGetSymbolAddress((void**)&h_p,      g_h);
    cudaGetSymbolAddress((void**)&t_p,      g_t);
    cudaGetSymbolAddress((void**)&agg_p,    g_agg);
    cudaGetSymbolAddress((void**)&ea_p,     g_EA);
    cudaGetSymbolAddress((void**)&sums_p,   g_sums);
    cudaGetSymbolAddress((void**)&counts_p, g_counts);

    const int nodeBlocks = (N + 7) / 8;

    cudaMemsetAsync(ea_p,     0, (size_t)N * 12 * sizeof(float), 0);
    cudaMemsetAsync(sums_p,   0, NGRAPH * sizeof(float), 0);
    cudaMemsetAsync(counts_p, 0, NGRAPH * sizeof(float), 0);

    k_readin<<<nodeBlocks, 256>>>(state, action, W_in, b_in, h_p, N);
    k_ea<<<(E * 3 + 255) / 256, 256>>>(edge_idx, edge_attr, ea_p, E);

    for (int l = 0; l < 2; l++) {
        k_matnbr<<<nodeBlocks, 256>>>(h_p, W_nbr + l * 64 * 64, t_p, N);
        cudaMemsetAsync(agg_p, 0, (size_t)N * CCH * sizeof(float), 0);
        k_scatter<<<(E * 16 + 255) / 256, 256>>>(edge_idx, t_p, agg_p, E);
        k_update<<<nodeBlocks, 256>>>(h_p, agg_p, ea_p,
                                      W_self + l * 64 * 64,
                                      W_edge + l * 12 * 64,
                                      b_conv + l * 64, N);
    }

    k_readout<<<nodeBlocks, 256>>>(h_p, W_out, b_out, batch, sums_p, counts_p, N);
    k_final<<<(G + 127) / 128, 128>>>(sums_p, counts_p, out, G);
}